// round 2
// baseline (speedup 1.0000x reference)
#include <cuda_runtime.h>
#include <cuda_bf16.h>
#include <cstdint>

// Problem dims (fixed by the reference)
#define VOCAB 50000
#define EDIM  64
#define HDIM  64
#define BATCH 1024
#define SEQ   512

// Scratch: projected table proj[v][h] = b_ih[h]+b_hh[h] + sum_e emb[v,e]*W_ih[h,e]
__device__ float g_proj[VOCAB * HDIM];   // 12.8 MB, L2-resident in steady state
__device__ int   g_x64flag;              // 1 if token buffer is int64, 0 if int32

// ---------------------------------------------------------------------------
// Kernel A: detect int32 vs int64 token layout.
// Tokens are in [0, 50000); for little-endian int64 every odd 32-bit word is
// 0. For int32 data the odd words are real tokens (P[all 64 == 0] ~ 0).
// ---------------------------------------------------------------------------
__global__ void detect_kernel(const int* __restrict__ x32) {
    if (threadIdx.x == 0 && blockIdx.x == 0) {
        int f = 1;
        for (int k = 0; k < 64; k++) {
            if (x32[2 * k + 1] != 0) { f = 0; break; }
        }
        g_x64flag = f;
    }
}

// ---------------------------------------------------------------------------
// Kernel B: build projected embedding table (fuses gather-side GEMM + biases).
// Block = 256 threads handles 32 vocab rows. W_ih cached in smem (stride 65,
// conflict-free), emb rows cached in smem.
// ---------------------------------------------------------------------------
#define PROJ_ROWS 32
__global__ __launch_bounds__(256) void proj_kernel(
    const float* __restrict__ emb,
    const float* __restrict__ W_ih,
    const float* __restrict__ b_ih,
    const float* __restrict__ b_hh)
{
    __shared__ float s_w[HDIM * 65];
    __shared__ float s_e[PROJ_ROWS * EDIM];
    __shared__ float s_bias[HDIM];

    const int t  = threadIdx.x;
    const int v0 = blockIdx.x * PROJ_ROWS;

    #pragma unroll
    for (int k = 0; k < 16; k++) {
        int idx = t + k * 256;                 // 0..4095
        int hg = idx >> 6, eg = idx & 63;
        s_w[hg * 65 + eg] = W_ih[idx];
    }
    #pragma unroll
    for (int k = 0; k < 8; k++) {
        int idx = t + k * 256;                 // 0..2047
        int r = idx >> 6, e = idx & 63;
        s_e[idx] = (v0 + r < VOCAB) ? emb[(long)(v0 + r) * EDIM + e] : 0.0f;
    }
    if (t < HDIM) s_bias[t] = b_ih[t] + b_hh[t];
    __syncthreads();

    const int h    = t & 63;
    const int rgrp = t >> 6;                   // 0..3
    #pragma unroll
    for (int k = 0; k < 8; k++) {
        int r = rgrp + 4 * k;                  // 0..31
        if (v0 + r >= VOCAB) break;
        float acc = s_bias[h];
        #pragma unroll
        for (int e = 0; e < EDIM; e++)
            acc += s_e[r * EDIM + e] * s_w[h * 65 + e];
        g_proj[(v0 + r) * HDIM + h] = acc;
    }
}

// ---------------------------------------------------------------------------
// Kernel C: recurrence + fc + sigmoid, TWO batch rows per block via packed
// fma.rn.f32x2 (FFMA2). 64 threads/block; thread i owns h[i] of both rows.
// W_hh row i duplicated into 64 packed 64-bit regs. h broadcast through
// double-buffered smem as float2 pairs (LDS.128 via ulonglong2).
// ---------------------------------------------------------------------------
__global__ __launch_bounds__(64) void rnn2_kernel(
    const int*   __restrict__ x32,
    const float* __restrict__ W_hh,
    const float* __restrict__ fc_w,
    const float* __restrict__ fc_b,
    float*       __restrict__ out)
{
    __shared__ int    s_tok[2][SEQ];
    __shared__ float2 s_h[2][HDIM];
    __shared__ float2 s_part[2];

    const int bp = blockIdx.x;            // 0..511
    const int b0 = 2 * bp, b1 = 2 * bp + 1;
    const int i  = threadIdx.x;
    const int flag = g_x64flag;

    // Preload both rows' tokens (handles int32 or int64 source layout)
    for (int t = i; t < SEQ; t += 64) {
        long baseA = (long)b0 * SEQ + t;
        long baseB = (long)b1 * SEQ + t;
        s_tok[0][t] = flag ? x32[2 * baseA] : x32[baseA];
        s_tok[1][t] = flag ? x32[2 * baseB] : x32[baseB];
    }

    // W_hh row i, each weight duplicated into a packed (w,w) 64-bit register
    unsigned long long wp[HDIM];
    {
        const float4* w4 = (const float4*)(W_hh + i * HDIM);
        #pragma unroll
        for (int q = 0; q < 16; q++) {
            float4 v = w4[q];
            asm("mov.b64 %0, {%1, %1};" : "=l"(wp[4 * q + 0]) : "f"(v.x));
            asm("mov.b64 %0, {%1, %1};" : "=l"(wp[4 * q + 1]) : "f"(v.y));
            asm("mov.b64 %0, {%1, %1};" : "=l"(wp[4 * q + 2]) : "f"(v.z));
            asm("mov.b64 %0, {%1, %1};" : "=l"(wp[4 * q + 3]) : "f"(v.w));
        }
    }

    s_h[0][i] = make_float2(0.0f, 0.0f);
    __syncthreads();

    float xpA = g_proj[s_tok[0][0] * HDIM + i];
    float xpB = g_proj[s_tok[1][0] * HDIM + i];
    float hA = 0.0f, hB = 0.0f;

    #pragma unroll 1
    for (int t = 0; t < SEQ; t++) {
        unsigned long long acc0, acc1 = 0ULL, acc2 = 0ULL, acc3 = 0ULL;
        asm("mov.b64 %0, {%1, %2};" : "=l"(acc0) : "f"(xpA), "f"(xpB));

        // Prefetch next step's projected rows (wraps harmlessly at t=511)
        int tn = (t + 1) & (SEQ - 1);
        xpA = g_proj[s_tok[0][tn] * HDIM + i];
        xpB = g_proj[s_tok[1][tn] * HDIM + i];

        const ulonglong2* hs2 = (const ulonglong2*)s_h[t & 1];
        #pragma unroll
        for (int j = 0; j < HDIM / 2; j += 2) {     // j indexes ulonglong2 pairs
            ulonglong2 p = hs2[j];
            ulonglong2 q = hs2[j + 1];
            asm("fma.rn.f32x2 %0, %1, %2, %0;" : "+l"(acc0) : "l"(p.x), "l"(wp[2 * j + 0]));
            asm("fma.rn.f32x2 %0, %1, %2, %0;" : "+l"(acc1) : "l"(p.y), "l"(wp[2 * j + 1]));
            asm("fma.rn.f32x2 %0, %1, %2, %0;" : "+l"(acc2) : "l"(q.x), "l"(wp[2 * j + 2]));
            asm("fma.rn.f32x2 %0, %1, %2, %0;" : "+l"(acc3) : "l"(q.y), "l"(wp[2 * j + 3]));
        }
        asm("add.rn.f32x2 %0, %0, %1;" : "+l"(acc0) : "l"(acc1));
        asm("add.rn.f32x2 %0, %0, %1;" : "+l"(acc2) : "l"(acc3));
        asm("add.rn.f32x2 %0, %0, %1;" : "+l"(acc0) : "l"(acc2));

        float aA, aB;
        asm("mov.b64 {%0, %1}, %2;" : "=f"(aA), "=f"(aB) : "l"(acc0));
        hA = tanhf(aA);
        hB = tanhf(aB);
        s_h[(t & 1) ^ 1][i] = make_float2(hA, hB);
        __syncthreads();
    }

    // fc + sigmoid for both rows
    float f = fc_w[i];
    float vA = hA * f, vB = hB * f;
    #pragma unroll
    for (int off = 16; off; off >>= 1) {
        vA += __shfl_xor_sync(0xffffffff, vA, off);
        vB += __shfl_xor_sync(0xffffffff, vB, off);
    }
    if ((i & 31) == 0) s_part[i >> 5] = make_float2(vA, vB);
    __syncthreads();
    if (i == 0) {
        float bias = fc_b[0];
        float lA = s_part[0].x + s_part[1].x + bias;
        float lB = s_part[0].y + s_part[1].y + bias;
        out[b0] = 1.0f / (1.0f + expf(-lA));
        out[b1] = 1.0f / (1.0f + expf(-lB));
    }
}

// ---------------------------------------------------------------------------
// Launch. Inputs (metadata order): x, emb, W_ih, W_hh, b_ih, b_hh, fc_w, fc_b
// ---------------------------------------------------------------------------
extern "C" void kernel_launch(void* const* d_in, const int* in_sizes, int n_in,
                              void* d_out, int out_size)
{
    const int*   x32  = (const int*)  d_in[0];
    const float* emb  = (const float*)d_in[1];
    const float* W_ih = (const float*)d_in[2];
    const float* W_hh = (const float*)d_in[3];
    const float* b_ih = (const float*)d_in[4];
    const float* b_hh = (const float*)d_in[5];
    const float* fc_w = (const float*)d_in[6];
    const float* fc_b = (const float*)d_in[7];
    float* out = (float*)d_out;

    detect_kernel<<<1, 32>>>(x32);
    proj_kernel<<<(VOCAB + PROJ_ROWS - 1) / PROJ_ROWS, 256>>>(emb, W_ih, b_ih, b_hh);
    rnn2_kernel<<<BATCH / 2, 64>>>(x32, W_hh, fc_w, fc_b, out);
}